// round 14
// baseline (speedup 1.0000x reference)
#include <cuda_runtime.h>

#define N_NODES 50000
#define N_EDGES 800000
#define D 64
#define NLAYERS 4
#define NGRAPHS 128
#define CAP 64           // max in-degree slots; Poisson(16) -> P(deg>=64) ~ 1e-21
#define NPAD 50048       // N_NODES rounded up to 128-node tiles (391*128)

// Scratch (all __device__ globals per harness rules)
__device__ float4 g_bufA[N_NODES * (D / 4)];
__device__ float4 g_bufB[N_NODES * (D / 4)];
__device__ uint4  g_bufS[NPAD * 32];           // 32 uint4/row = 64 (hi,lo) tf32 pairs
__device__ unsigned g_Wsplit[NLAYERS * D * 136];
__device__ int g_counts[2][N_NODES];
__device__ int g_bucket[2][N_NODES * CAP];

// ---------------------------------------------------------------------------
// tf32 helpers
// ---------------------------------------------------------------------------
__device__ __forceinline__ unsigned f2tf32(float x) {
    unsigned r;
    asm("cvt.rna.tf32.f32 %0, %1;" : "=r"(r) : "f"(x));
    return r;
}

__device__ __forceinline__ void mma_tf32(float c[4],
                                         unsigned a0, unsigned a1, unsigned a2, unsigned a3,
                                         unsigned b0, unsigned b1) {
    asm volatile(
        "mma.sync.aligned.m16n8k8.row.col.f32.tf32.tf32.f32 "
        "{%0,%1,%2,%3}, {%4,%5,%6,%7}, {%8,%9}, {%0,%1,%2,%3};"
        : "+f"(c[0]), "+f"(c[1]), "+f"(c[2]), "+f"(c[3])
        : "r"(a0), "r"(a1), "r"(a2), "r"(a3), "r"(b0), "r"(b1));
}

// ---------------------------------------------------------------------------
// One-time per launch: split all layers' W into (hi,lo) tf32 pairs, padded rows.
// ---------------------------------------------------------------------------
__global__ void wsplit_kernel(const float* __restrict__ Ws, unsigned* __restrict__ Wsplit) {
    int i = blockIdx.x * blockDim.x + threadIdx.x;
    if (i >= NLAYERS * D * D) return;
    int l = i >> 12;            // / (D*D)
    int r = i & 4095;
    int o = r >> 6, k = r & 63;
    float x = Ws[i];
    unsigned hi = f2tf32(x);
    unsigned lo = f2tf32(x - __uint_as_float(hi));
    unsigned* row = Wsplit + l * D * 136 + o * 136;
    row[2 * k] = hi;
    row[2 * k + 1] = lo;
}

// ---------------------------------------------------------------------------
// Scan-free adjacency build: fixed-capacity buckets, rebuilt every launch.
// ---------------------------------------------------------------------------
__global__ void zero_counts_kernel(int* c0, int* c1) {
    int i = blockIdx.x * blockDim.x + threadIdx.x;
    if (i < N_NODES) { c0[i] = 0; c1[i] = 0; }
}

__global__ void build_kernel(const int* __restrict__ src0, const int* __restrict__ dst0,
                             const int* __restrict__ src1, const int* __restrict__ dst1,
                             int* c0, int* c1, int* b0, int* b1) {
    int e = blockIdx.x * blockDim.x + threadIdx.x;
    if (e >= N_EDGES) return;
    if (blockIdx.y == 0) {
        int d = dst0[e];
        int slot = atomicAdd(&c0[d], 1);
        if (slot < CAP) b0[d * CAP + slot] = src0[e];
    } else {
        int d = dst1[e];
        int slot = atomicAdd(&c1[d], 1);
        if (slot < CAP) b1[d * CAP + slot] = src1[e];
    }
}

// ---------------------------------------------------------------------------
// GIN aggregate gather core
// ---------------------------------------------------------------------------
__device__ __forceinline__ float4 gather_core(const float4* __restrict__ x,
                                              int n, int lane,
                                              const int* __restrict__ cnt,
                                              const int* __restrict__ bucket) {
    int deg = cnt[n];
    if (deg > CAP) deg = CAP;
    const int* __restrict__ lst = bucket + n * CAP;
    float4 acc = x[n * 16 + lane];
    int j = 0;
    for (; j + 4 <= deg; j += 4) {
        int s0 = lst[j];
        int s1 = lst[j + 1];
        int s2 = lst[j + 2];
        int s3 = lst[j + 3];
        float4 v0 = x[s0 * 16 + lane];
        float4 v1 = x[s1 * 16 + lane];
        float4 v2 = x[s2 * 16 + lane];
        float4 v3 = x[s3 * 16 + lane];
        acc.x += (v0.x + v1.x) + (v2.x + v3.x);
        acc.y += (v0.y + v1.y) + (v2.y + v3.y);
        acc.z += (v0.z + v1.z) + (v2.z + v3.z);
        acc.w += (v0.w + v1.w) + (v2.w + v3.w);
    }
    for (; j < deg; j++) {
        int s = lst[j];
        float4 v = x[s * 16 + lane];
        acc.x += v.x; acc.y += v.y; acc.z += v.z; acc.w += v.w;
    }
    return acc;
}

// Real-graph gather: emit (hi,lo) tf32 pairs for the MMA GEMM.
__global__ void gather_split_kernel(const float4* __restrict__ x,
                                    const int* __restrict__ cnt,
                                    const int* __restrict__ bucket,
                                    uint4* __restrict__ outS) {
    int lane = threadIdx.x & 15;
    int n = blockIdx.x * 16 + (threadIdx.x >> 4);
    if (n >= N_NODES) return;
    float4 acc = gather_core(x, n, lane, cnt, bucket);
    unsigned h0 = f2tf32(acc.x), h1 = f2tf32(acc.y), h2 = f2tf32(acc.z), h3 = f2tf32(acc.w);
    unsigned l0 = f2tf32(acc.x - __uint_as_float(h0));
    unsigned l1 = f2tf32(acc.y - __uint_as_float(h1));
    unsigned l2 = f2tf32(acc.z - __uint_as_float(h2));
    unsigned l3 = f2tf32(acc.w - __uint_as_float(h3));
    outS[n * 32 + 2 * lane]     = make_uint4(h0, l0, h1, l1);
    outS[n * 32 + 2 * lane + 1] = make_uint4(h2, l2, h3, l3);
}

// Expander gather: plain fp32 output.
__global__ void gather_kernel(const float4* __restrict__ x,
                              const int* __restrict__ cnt,
                              const int* __restrict__ bucket,
                              float4* __restrict__ out) {
    int lane = threadIdx.x & 15;
    int n = blockIdx.x * 16 + (threadIdx.x >> 4);
    if (n >= N_NODES) return;
    float4 acc = gather_core(x, n, lane, cnt, bucket);
    out[n * 16 + lane] = acc;
}

// ---------------------------------------------------------------------------
// out = relu(in @ W^T + b) via 3xTF32 MMA.
// A fragments LDG'd directly from pre-split gather output (no A smem).
// W pre-split globally; block stages it by pure uint4 copy.
// 128-node tile, 512 threads (16 warps = 8 m-tiles x 2 n-halves).
// Rows >= N_NODES read in-bounds pad garbage; their stores are guarded.
// ---------------------------------------------------------------------------
__global__ void __launch_bounds__(512, 2)
gemm_relu_kernel(const uint2* __restrict__ aS,      // [row][64] (hi,lo) pairs
                 const unsigned* __restrict__ Wsp,  // [64][136] (hi,lo) pairs
                 const float* __restrict__ bias,
                 float* __restrict__ out) {
    __shared__ unsigned sW[D * 136];
    const int tid = threadIdx.x;
    const int nodeBase = blockIdx.x * 128;

    // Stage W: straight uint4 copy (no cvt). 8704 u32 = 2176 uint4.
    for (int i = tid; i < D * 136 / 4; i += 512)
        ((uint4*)sW)[i] = ((const uint4*)Wsp)[i];
    __syncthreads();

    const int warp = tid >> 5;
    const int lane = tid & 31;
    const int grp  = lane >> 2;      // 0..7
    const int tig  = lane & 3;       // 0..3
    const int m    = warp & 7;       // m-tile: rows m*16 .. m*16+15
    const int h    = warp >> 3;      // n-half: dims h*32 .. h*32+31
    const int row0 = nodeBase + m * 16 + grp;
    const int row1 = row0 + 8;

    float c[4][4];
#pragma unroll
    for (int nt = 0; nt < 4; nt++)
#pragma unroll
        for (int q = 0; q < 4; q++) c[nt][q] = 0.f;

#pragma unroll
    for (int kc = 0; kc < 8; kc++) {
        const int k0 = kc * 8;
        uint2 a0 = aS[row0 * 64 + k0 + tig];        // (hi,lo)
        uint2 a1 = aS[row1 * 64 + k0 + tig];
        uint2 a2 = aS[row0 * 64 + k0 + tig + 4];
        uint2 a3 = aS[row1 * 64 + k0 + tig + 4];
#pragma unroll
        for (int nt = 0; nt < 4; nt++) {
            const int o = h * 32 + nt * 8 + grp;
            uint2 b0 = *(const uint2*)&sW[o * 136 + 2 * (k0 + tig)];
            uint2 b1 = *(const uint2*)&sW[o * 136 + 2 * (k0 + tig + 4)];
            mma_tf32(c[nt], a0.x, a1.x, a2.x, a3.x, b0.x, b1.x);   // hi*hi
            mma_tf32(c[nt], a0.y, a1.y, a2.y, a3.y, b0.x, b1.x);   // lo*hi
            mma_tf32(c[nt], a0.x, a1.x, a2.x, a3.x, b0.y, b1.y);   // hi*lo
        }
    }

    // Epilogue: bias + relu + store (c0,c1 -> row0; c2,c3 -> row1)
#pragma unroll
    for (int nt = 0; nt < 4; nt++) {
        int o = h * 32 + nt * 8 + 2 * tig;
        float2 bv = *(const float2*)&bias[o];
        if (row0 < N_NODES) {
            float2 v = make_float2(fmaxf(c[nt][0] + bv.x, 0.f),
                                   fmaxf(c[nt][1] + bv.y, 0.f));
            *(float2*)&out[row0 * D + o] = v;
        }
        if (row1 < N_NODES) {
            float2 v = make_float2(fmaxf(c[nt][2] + bv.x, 0.f),
                                   fmaxf(c[nt][3] + bv.y, 0.f));
            *(float2*)&out[row1 * D + o] = v;
        }
    }
}

// ---------------------------------------------------------------------------
__global__ void zero_out_kernel(float* __restrict__ out, int n) {
    int i = blockIdx.x * blockDim.x + threadIdx.x;
    if (i < n) out[i] = 0.0f;
}

// batch is sorted: register accumulator, flush on graph-id change only.
__global__ void pool_kernel(const float* __restrict__ x,
                            const int* __restrict__ batch,
                            float* __restrict__ out, int chunk) {
    int d = threadIdx.x;
    int n0 = blockIdx.x * chunk;
    int n1 = n0 + chunk;
    if (n1 > N_NODES) n1 = N_NODES;
    if (n0 >= n1) return;
    float acc = 0.0f;
    int cur = batch[n0];
    for (int n = n0; n < n1; n++) {
        int g = batch[n];
        if (g != cur) {
            atomicAdd(&out[cur * D + d], acc);
            acc = 0.0f;
            cur = g;
        }
        acc += x[n * D + d];
    }
    atomicAdd(&out[cur * D + d], acc);
}

// ---------------------------------------------------------------------------
extern "C" void kernel_launch(void* const* d_in, const int* in_sizes, int n_in,
                              void* d_out, int out_size) {
    const float* x     = (const float*)d_in[0];
    const int*   ei    = (const int*)d_in[1];
    const int*   eei   = (const int*)d_in[2];
    const int*   batch = (const int*)d_in[3];
    const float* Ws    = (const float*)d_in[4];
    const float* bs    = (const float*)d_in[5];
    float*       out   = (float*)d_out;

    float4 *bufA, *bufB;
    uint4* bufS;
    unsigned* wsp;
    int *counts, *bucket;
    cudaGetSymbolAddress((void**)&bufA, g_bufA);
    cudaGetSymbolAddress((void**)&bufB, g_bufB);
    cudaGetSymbolAddress((void**)&bufS, g_bufS);
    cudaGetSymbolAddress((void**)&wsp, g_Wsplit);
    cudaGetSymbolAddress((void**)&counts, g_counts);
    cudaGetSymbolAddress((void**)&bucket, g_bucket);
    int *c0 = counts, *c1 = counts + N_NODES;
    int *b0 = bucket, *b1 = bucket + N_NODES * CAP;

    const int* src1 = ei;   const int* dst1 = ei + N_EDGES;
    const int* src2 = eei;  const int* dst2 = eei + N_EDGES;

    // ---- One-time prep: W split + bucket adjacency ----
    wsplit_kernel<<<(NLAYERS * D * D + 255) / 256, 256>>>(Ws, wsp);
    const int nBlocks = (N_NODES + 255) / 256;
    const int eBlocks = (N_EDGES + 255) / 256;
    zero_counts_kernel<<<nBlocks, 256>>>(c0, c1);
    build_kernel<<<dim3(eBlocks, 2), 256>>>(src1, dst1, src2, dst2, c0, c1, b0, b1);

    // ---- 4 layers ----
    const int gatherBlocks = (N_NODES + 15) / 16;
    const int gemmBlocks = (N_NODES + 127) / 128;

    const float4* xcur = (const float4*)x;
    for (int i = 0; i < NLAYERS; i++) {
        gather_split_kernel<<<gatherBlocks, 256>>>(xcur, c0, b0, bufS);
        gemm_relu_kernel<<<gemmBlocks, 512>>>((const uint2*)bufS, wsp + i * D * 136,
                                              bs + i * D, (float*)bufB);
        gather_kernel<<<gatherBlocks, 256>>>(bufB, c1, b1, bufA);
        xcur = bufA;
    }

    zero_out_kernel<<<(NGRAPHS * D + 255) / 256, 256>>>(out, NGRAPHS * D);
    pool_kernel<<<(N_NODES + 127) / 128, 64>>>((const float*)xcur, batch, out, 128);
}

// round 15
// speedup vs baseline: 1.4401x; 1.4401x over previous
#include <cuda_runtime.h>

#define N_NODES 50000
#define N_EDGES 800000
#define D 64
#define NLAYERS 4
#define NGRAPHS 128
#define PAD 68
#define CAP 64   // max in-degree slots; Poisson(16) -> P(deg>=64) ~ 1e-21

// Scratch (all __device__ globals per harness rules)
__device__ float4 g_bufA[N_NODES * (D / 4)];
__device__ float4 g_bufB[N_NODES * (D / 4)];
__device__ float4 g_bufC[N_NODES * (D / 4)];
__device__ int g_counts[2][N_NODES];
__device__ int g_bucket[2][N_NODES * CAP];

// ---------------------------------------------------------------------------
// Merged zeroing: adjacency counters for both graphs + pooled output.
// ---------------------------------------------------------------------------
__global__ void zero_kernel(int* c0, int* c1, float* out) {
    int i = blockIdx.x * blockDim.x + threadIdx.x;
    if (i < N_NODES) { c0[i] = 0; c1[i] = 0; }
    if (i < NGRAPHS * D) out[i] = 0.0f;
}

__global__ void build_kernel(const int* __restrict__ src0, const int* __restrict__ dst0,
                             const int* __restrict__ src1, const int* __restrict__ dst1,
                             int* c0, int* c1, int* b0, int* b1) {
    int e = blockIdx.x * blockDim.x + threadIdx.x;
    if (e >= N_EDGES) return;
    if (blockIdx.y == 0) {
        int d = dst0[e];
        int slot = atomicAdd(&c0[d], 1);
        if (slot < CAP) b0[d * CAP + slot] = src0[e];
    } else {
        int d = dst1[e];
        int slot = atomicAdd(&c1[d], 1);
        if (slot < CAP) b1[d * CAP + slot] = src1[e];
    }
}

// ---------------------------------------------------------------------------
// GIN aggregate as pure gather: out[n] = x[n] + sum_{e: dst=n} x[src[e]]
// ---------------------------------------------------------------------------
__global__ void gather_kernel(const float4* __restrict__ x,
                              const int* __restrict__ cnt,
                              const int* __restrict__ bucket,
                              float4* __restrict__ out) {
    int lane = threadIdx.x & 15;
    int n = blockIdx.x * 16 + (threadIdx.x >> 4);
    if (n >= N_NODES) return;
    int deg = cnt[n];
    if (deg > CAP) deg = CAP;
    const int* __restrict__ lst = bucket + n * CAP;
    float4 acc = x[n * 16 + lane];
    int j = 0;
    for (; j + 4 <= deg; j += 4) {
        int s0 = lst[j];
        int s1 = lst[j + 1];
        int s2 = lst[j + 2];
        int s3 = lst[j + 3];
        float4 v0 = x[s0 * 16 + lane];
        float4 v1 = x[s1 * 16 + lane];
        float4 v2 = x[s2 * 16 + lane];
        float4 v3 = x[s3 * 16 + lane];
        acc.x += (v0.x + v1.x) + (v2.x + v3.x);
        acc.y += (v0.y + v1.y) + (v2.y + v3.y);
        acc.z += (v0.z + v1.z) + (v2.z + v3.z);
        acc.w += (v0.w + v1.w) + (v2.w + v3.w);
    }
    for (; j < deg; j++) {
        int s = lst[j];
        float4 v = x[s * 16 + lane];
        acc.x += v.x; acc.y += v.y; acc.z += v.z; acc.w += v.w;
    }
    out[n * 16 + lane] = acc;
}

// ---------------------------------------------------------------------------
// out = relu(in @ W^T + b). 64 nodes/block, 256 threads, 4x4 register tile.
// A is read DIRECTLY from global (separate out buffer -> no in-place hazard):
// lanes with equal ty load identical addresses (broadcast-coalesced), and the
// fully unrolled k-loop gives ~64 independent LDG.128 => L2 latency hidden.
// Only W is staged in smem (17 KB) -> high occupancy.
// ---------------------------------------------------------------------------
__global__ void __launch_bounds__(256)
gemm_relu_kernel(const float* __restrict__ in,
                 const float* __restrict__ W,
                 const float* __restrict__ bias,
                 float* __restrict__ out) {
    __shared__ float sW[D * PAD];
    const int tid = threadIdx.x;
    const int tx = tid & 15;      // dims {tx, tx+16, tx+32, tx+48}
    const int ty = tid >> 4;      // nodes {4ty .. 4ty+3}
    const int nodeBase = blockIdx.x * 64;

    for (int i = tid; i < D * 16; i += 256) {
        int o = i >> 4, kv = (i & 15) * 4;
        *(float4*)&sW[o * PAD + kv] = *(const float4*)&W[o * D + kv];
    }
    __syncthreads();

    // Clamp row indices for loads (stores are guarded).
    int row[4];
#pragma unroll
    for (int r = 0; r < 4; r++) {
        int node = nodeBase + ty * 4 + r;
        row[r] = (node < N_NODES) ? node : (N_NODES - 1);
    }

    float acc[4][4];
#pragma unroll
    for (int r = 0; r < 4; r++)
#pragma unroll
        for (int c = 0; c < 4; c++) acc[r][c] = 0.f;

#pragma unroll
    for (int k = 0; k < D; k += 4) {
        float4 a[4], w[4];
#pragma unroll
        for (int r = 0; r < 4; r++) a[r] = *(const float4*)&in[row[r] * D + k];
#pragma unroll
        for (int c = 0; c < 4; c++) w[c] = *(const float4*)&sW[(tx + 16 * c) * PAD + k];
#pragma unroll
        for (int r = 0; r < 4; r++)
#pragma unroll
            for (int c = 0; c < 4; c++) {
                acc[r][c] = fmaf(a[r].x, w[c].x, acc[r][c]);
                acc[r][c] = fmaf(a[r].y, w[c].y, acc[r][c]);
                acc[r][c] = fmaf(a[r].z, w[c].z, acc[r][c]);
                acc[r][c] = fmaf(a[r].w, w[c].w, acc[r][c]);
            }
    }

    float bv[4];
#pragma unroll
    for (int c = 0; c < 4; c++) bv[c] = bias[tx + 16 * c];

#pragma unroll
    for (int r = 0; r < 4; r++) {
        int node = nodeBase + ty * 4 + r;
        if (node < N_NODES) {
#pragma unroll
            for (int c = 0; c < 4; c++)
                out[node * D + tx + 16 * c] = fmaxf(acc[r][c] + bv[c], 0.f);
        }
    }
}

// ---------------------------------------------------------------------------
// batch is sorted: register accumulator, flush on graph-id change only.
// ---------------------------------------------------------------------------
__global__ void pool_kernel(const float* __restrict__ x,
                            const int* __restrict__ batch,
                            float* __restrict__ out, int chunk) {
    int d = threadIdx.x;
    int n0 = blockIdx.x * chunk;
    int n1 = n0 + chunk;
    if (n1 > N_NODES) n1 = N_NODES;
    if (n0 >= n1) return;
    float acc = 0.0f;
    int cur = batch[n0];
    for (int n = n0; n < n1; n++) {
        int g = batch[n];
        if (g != cur) {
            atomicAdd(&out[cur * D + d], acc);
            acc = 0.0f;
            cur = g;
        }
        acc += x[n * D + d];
    }
    atomicAdd(&out[cur * D + d], acc);
}

// ---------------------------------------------------------------------------
extern "C" void kernel_launch(void* const* d_in, const int* in_sizes, int n_in,
                              void* d_out, int out_size) {
    const float* x     = (const float*)d_in[0];
    const int*   ei    = (const int*)d_in[1];
    const int*   eei   = (const int*)d_in[2];
    const int*   batch = (const int*)d_in[3];
    const float* Ws    = (const float*)d_in[4];
    const float* bs    = (const float*)d_in[5];
    float*       out   = (float*)d_out;

    float4 *bufA, *bufB, *bufC;
    int *counts, *bucket;
    cudaGetSymbolAddress((void**)&bufA, g_bufA);
    cudaGetSymbolAddress((void**)&bufB, g_bufB);
    cudaGetSymbolAddress((void**)&bufC, g_bufC);
    cudaGetSymbolAddress((void**)&counts, g_counts);
    cudaGetSymbolAddress((void**)&bucket, g_bucket);
    int *c0 = counts, *c1 = counts + N_NODES;
    int *b0 = bucket, *b1 = bucket + N_NODES * CAP;

    const int* src1 = ei;   const int* dst1 = ei + N_EDGES;
    const int* src2 = eei;  const int* dst2 = eei + N_EDGES;

    // ---- Build bucket adjacency for both graphs (scan-free) + zero out ----
    const int nBlocks = (N_NODES + 255) / 256;
    const int eBlocks = (N_EDGES + 255) / 256;
    zero_kernel<<<nBlocks, 256>>>(c0, c1, out);
    build_kernel<<<dim3(eBlocks, 2), 256>>>(src1, dst1, src2, dst2, c0, c1, b0, b1);

    // ---- 4 layers: real gather -> GEMM(+relu) -> expander gather ----
    const int gatherBlocks = (N_NODES + 15) / 16;
    const int gemmBlocks = (N_NODES + 63) / 64;

    const float4* xcur = (const float4*)x;
    for (int i = 0; i < NLAYERS; i++) {
        gather_kernel<<<gatherBlocks, 256>>>(xcur, c0, b0, bufB);
        gemm_relu_kernel<<<gemmBlocks, 256>>>((const float*)bufB, Ws + i * D * D,
                                              bs + i * D, (float*)bufC);
        gather_kernel<<<gatherBlocks, 256>>>(bufC, c1, b1, bufA);
        xcur = bufA;
    }

    pool_kernel<<<(N_NODES + 127) / 128, 64>>>((const float*)xcur, batch, out, 128);
}

// round 16
// speedup vs baseline: 1.7053x; 1.1842x over previous
#include <cuda_runtime.h>

#define N_NODES 50000
#define N_EDGES 800000
#define D 64
#define NLAYERS 4
#define NGRAPHS 128
#define CAP 64   // max in-degree slots; Poisson(16) -> P(deg>=64) ~ 1e-21

// Pair-row stride: 36 uint2 (72 words ≡ 8 banks) -> conflict-free LDS.64 phases
#define PSTR 36
#define GEMM_SMEM_BYTES ((128 * PSTR + 64 * PSTR) * 8)   // 55296

// Scratch (all __device__ globals per harness rules) — two feature buffers only.
__device__ float4 g_bufA[N_NODES * (D / 4)];
__device__ float4 g_bufB[N_NODES * (D / 4)];
__device__ int g_counts[2][N_NODES];
__device__ int g_bucket[2][N_NODES * CAP];

// ---------------------------------------------------------------------------
// tf32 helpers
// ---------------------------------------------------------------------------
__device__ __forceinline__ unsigned f2tf32(float x) {
    unsigned r;
    asm("cvt.rna.tf32.f32 %0, %1;" : "=r"(r) : "f"(x));
    return r;
}

__device__ __forceinline__ void mma_tf32(float c[4],
                                         unsigned a0, unsigned a1, unsigned a2, unsigned a3,
                                         unsigned b0, unsigned b1) {
    asm volatile(
        "mma.sync.aligned.m16n8k8.row.col.f32.tf32.tf32.f32 "
        "{%0,%1,%2,%3}, {%4,%5,%6,%7}, {%8,%9}, {%0,%1,%2,%3};"
        : "+f"(c[0]), "+f"(c[1]), "+f"(c[2]), "+f"(c[3])
        : "r"(a0), "r"(a1), "r"(a2), "r"(a3), "r"(b0), "r"(b1));
}

// ---------------------------------------------------------------------------
// Merged zeroing: adjacency counters for both graphs + pooled output.
// ---------------------------------------------------------------------------
__global__ void zero_kernel(int* c0, int* c1, float* out) {
    int i = blockIdx.x * blockDim.x + threadIdx.x;
    if (i < N_NODES) { c0[i] = 0; c1[i] = 0; }
    if (i < NGRAPHS * D) out[i] = 0.0f;
}

__global__ void build_kernel(const int* __restrict__ src0, const int* __restrict__ dst0,
                             const int* __restrict__ src1, const int* __restrict__ dst1,
                             int* c0, int* c1, int* b0, int* b1) {
    int e = blockIdx.x * blockDim.x + threadIdx.x;
    if (e >= N_EDGES) return;
    if (blockIdx.y == 0) {
        int d = dst0[e];
        int slot = atomicAdd(&c0[d], 1);
        if (slot < CAP) b0[d * CAP + slot] = src0[e];
    } else {
        int d = dst1[e];
        int slot = atomicAdd(&c1[d], 1);
        if (slot < CAP) b1[d * CAP + slot] = src1[e];
    }
}

// ---------------------------------------------------------------------------
// GIN aggregate as pure gather: out[n] = x[n] + sum_{e: dst=n} x[src[e]]
// ---------------------------------------------------------------------------
__global__ void gather_kernel(const float4* __restrict__ x,
                              const int* __restrict__ cnt,
                              const int* __restrict__ bucket,
                              float4* __restrict__ out) {
    int lane = threadIdx.x & 15;
    int n = blockIdx.x * 16 + (threadIdx.x >> 4);
    if (n >= N_NODES) return;
    int deg = cnt[n];
    if (deg > CAP) deg = CAP;
    const int* __restrict__ lst = bucket + n * CAP;
    float4 acc = x[n * 16 + lane];
    int j = 0;
    for (; j + 4 <= deg; j += 4) {
        int s0 = lst[j];
        int s1 = lst[j + 1];
        int s2 = lst[j + 2];
        int s3 = lst[j + 3];
        float4 v0 = x[s0 * 16 + lane];
        float4 v1 = x[s1 * 16 + lane];
        float4 v2 = x[s2 * 16 + lane];
        float4 v3 = x[s3 * 16 + lane];
        acc.x += (v0.x + v1.x) + (v2.x + v3.x);
        acc.y += (v0.y + v1.y) + (v2.y + v3.y);
        acc.z += (v0.z + v1.z) + (v2.z + v3.z);
        acc.w += (v0.w + v1.w) + (v2.w + v3.w);
    }
    for (; j < deg; j++) {
        int s = lst[j];
        float4 v = x[s * 16 + lane];
        acc.x += v.x; acc.y += v.y; acc.z += v.z; acc.w += v.w;
    }
    out[n * 16 + lane] = acc;
}

// ---------------------------------------------------------------------------
// out = relu(in @ W^T + b) via SINGLE-PASS TF32 MMA (m16n8k8).
// 128-node tile, 512 threads (16 warps = 8 m-tiles x 2 n-halves).
// A and W staged in smem as tf32 (k, k+4) uint2 pairs; inner loop is pure
// LDS.64 + HMMA (6 LDS + 4 MMA per kc per thread).
// In-place safe (full tile staged before any store by this block).
// ---------------------------------------------------------------------------
__global__ void __launch_bounds__(512, 2)
gemm_relu_kernel(const float* __restrict__ in,
                 const float* __restrict__ W,
                 const float* __restrict__ bias,
                 float* __restrict__ out) {
    extern __shared__ unsigned sm[];
    unsigned* sA = sm;                       // [128][PSTR] uint2: (tf32 k, tf32 k+4)
    unsigned* sW = sm + 128 * PSTR * 2;      // [64][PSTR] uint2
    const int tid = threadIdx.x;
    const int nodeBase = blockIdx.x * 128;

    // Stage W: cvt to tf32 pairs. elem k -> pair (k>>3)*4 + (k&3), half (k>>2)&1.
    for (int i = tid; i < D * 16; i += 512) {
        int o = i >> 4, kv = (i & 15) * 4;
        float4 v = *(const float4*)&W[o * D + kv];
        int p0 = (kv >> 3) * 4;
        int half = (kv >> 2) & 1;
        unsigned* base = &sW[(o * PSTR + p0) * 2 + half];
        base[0] = f2tf32(v.x);
        base[2] = f2tf32(v.y);
        base[4] = f2tf32(v.z);
        base[6] = f2tf32(v.w);
    }
    // Stage A tile (zero-fill past N_NODES).
    for (int i = tid; i < 128 * 16; i += 512) {
        int r = i >> 4, kv = (i & 15) * 4;
        int node = nodeBase + r;
        float4 v = make_float4(0.f, 0.f, 0.f, 0.f);
        if (node < N_NODES) v = *(const float4*)&in[node * D + kv];
        int p0 = (kv >> 3) * 4;
        int half = (kv >> 2) & 1;
        unsigned* base = &sA[(r * PSTR + p0) * 2 + half];
        base[0] = f2tf32(v.x);
        base[2] = f2tf32(v.y);
        base[4] = f2tf32(v.z);
        base[6] = f2tf32(v.w);
    }
    __syncthreads();

    const int warp = tid >> 5;
    const int lane = tid & 31;
    const int grp  = lane >> 2;      // 0..7
    const int tig  = lane & 3;       // 0..3
    const int m    = warp & 7;       // m-tile: rows m*16 .. m*16+15
    const int h    = warp >> 3;      // n-half: dims h*32 .. h*32+31
    const int row0 = m * 16 + grp;
    const int row1 = row0 + 8;

    float c[4][4];
#pragma unroll
    for (int nt = 0; nt < 4; nt++)
#pragma unroll
        for (int q = 0; q < 4; q++) c[nt][q] = 0.f;

#pragma unroll
    for (int kc = 0; kc < 8; kc++) {
        const int p = kc * 4 + tig;
        uint2 a0 = *(const uint2*)&sA[(row0 * PSTR + p) * 2];   // (A[k], A[k+4])
        uint2 a1 = *(const uint2*)&sA[(row1 * PSTR + p) * 2];
#pragma unroll
        for (int nt = 0; nt < 4; nt++) {
            const int o = h * 32 + nt * 8 + grp;
            uint2 b = *(const uint2*)&sW[(o * PSTR + p) * 2];   // (W[k], W[k+4])
            mma_tf32(c[nt], a0.x, a1.x, a0.y, a1.y, b.x, b.y);
        }
    }

    // Epilogue: bias + relu + store (c0,c1 -> row0; c2,c3 -> row1)
    const int n0 = nodeBase + row0;
    const int n1 = nodeBase + row1;
#pragma unroll
    for (int nt = 0; nt < 4; nt++) {
        int o = h * 32 + nt * 8 + 2 * tig;
        float2 bv = *(const float2*)&bias[o];
        if (n0 < N_NODES) {
            float2 v = make_float2(fmaxf(c[nt][0] + bv.x, 0.f),
                                   fmaxf(c[nt][1] + bv.y, 0.f));
            *(float2*)&out[n0 * D + o] = v;
        }
        if (n1 < N_NODES) {
            float2 v = make_float2(fmaxf(c[nt][2] + bv.x, 0.f),
                                   fmaxf(c[nt][3] + bv.y, 0.f));
            *(float2*)&out[n1 * D + o] = v;
        }
    }
}

// ---------------------------------------------------------------------------
// batch is sorted: register accumulator, flush on graph-id change only.
// ---------------------------------------------------------------------------
__global__ void pool_kernel(const float* __restrict__ x,
                            const int* __restrict__ batch,
                            float* __restrict__ out, int chunk) {
    int d = threadIdx.x;
    int n0 = blockIdx.x * chunk;
    int n1 = n0 + chunk;
    if (n1 > N_NODES) n1 = N_NODES;
    if (n0 >= n1) return;
    float acc = 0.0f;
    int cur = batch[n0];
    for (int n = n0; n < n1; n++) {
        int g = batch[n];
        if (g != cur) {
            atomicAdd(&out[cur * D + d], acc);
            acc = 0.0f;
            cur = g;
        }
        acc += x[n * D + d];
    }
    atomicAdd(&out[cur * D + d], acc);
}

// ---------------------------------------------------------------------------
extern "C" void kernel_launch(void* const* d_in, const int* in_sizes, int n_in,
                              void* d_out, int out_size) {
    const float* x     = (const float*)d_in[0];
    const int*   ei    = (const int*)d_in[1];
    const int*   eei   = (const int*)d_in[2];
    const int*   batch = (const int*)d_in[3];
    const float* Ws    = (const float*)d_in[4];
    const float* bs    = (const float*)d_in[5];
    float*       out   = (float*)d_out;

    // Raise dynamic-smem limit (idempotent; not an allocation).
    cudaFuncSetAttribute(gemm_relu_kernel,
                         cudaFuncAttributeMaxDynamicSharedMemorySize, GEMM_SMEM_BYTES);

    float4 *bufA, *bufB;
    int *counts, *bucket;
    cudaGetSymbolAddress((void**)&bufA, g_bufA);
    cudaGetSymbolAddress((void**)&bufB, g_bufB);
    cudaGetSymbolAddress((void**)&counts, g_counts);
    cudaGetSymbolAddress((void**)&bucket, g_bucket);
    int *c0 = counts, *c1 = counts + N_NODES;
    int *b0 = bucket, *b1 = bucket + N_NODES * CAP;

    const int* src1 = ei;   const int* dst1 = ei + N_EDGES;
    const int* src2 = eei;  const int* dst2 = eei + N_EDGES;

    // ---- Build bucket adjacency (scan-free) + zero pooled output ----
    const int nBlocks = (N_NODES + 255) / 256;
    const int eBlocks = (N_EDGES + 255) / 256;
    zero_kernel<<<nBlocks, 256>>>(c0, c1, out);
    build_kernel<<<dim3(eBlocks, 2), 256>>>(src1, dst1, src2, dst2, c0, c1, b0, b1);

    // ---- 4 layers: real gather -> TF32 GEMM(+relu, in place) -> expander gather ----
    const int gatherBlocks = (N_NODES + 15) / 16;
    const int gemmBlocks = (N_NODES + 127) / 128;

    const float4* xcur = (const float4*)x;
    for (int i = 0; i < NLAYERS; i++) {
        gather_kernel<<<gatherBlocks, 256>>>(xcur, c0, b0, bufB);
        gemm_relu_kernel<<<gemmBlocks, 512, GEMM_SMEM_BYTES>>>((const float*)bufB,
                                                               Ws + i * D * D,
                                                               bs + i * D, (float*)bufB);
        gather_kernel<<<gatherBlocks, 256>>>(bufB, c1, b1, bufA);
        xcur = bufA;
    }

    pool_kernel<<<(N_NODES + 127) / 128, 64>>>((const float*)xcur, batch, out, 128);
}

// round 17
// speedup vs baseline: 1.7199x; 1.0085x over previous
#include <cuda_runtime.h>

#define N_NODES 50000
#define N_EDGES 800000
#define D 64
#define NLAYERS 4
#define NGRAPHS 128
#define CAP 64   // max in-degree slots; Poisson(16) -> P(deg>=64) ~ 1e-21

// Pair-row stride: 36 uint2 (72 words ≡ 8 banks) -> conflict-free LDS.64 phases
#define PSTR 36
#define GEMM_SMEM_BYTES ((128 * PSTR + 64 * PSTR) * 8)   // 55296
#define WROW_U4 (PSTR / 2)                                // 18 uint4 per W row
#define WLAYER_U4 (D * WROW_U4)                           // 1152 uint4 per layer

// Scratch (all __device__ globals per harness rules) — two feature buffers only.
__device__ float4 g_bufA[N_NODES * (D / 4)];
__device__ float4 g_bufB[N_NODES * (D / 4)];
__device__ uint4  g_Wpair[NLAYERS * WLAYER_U4];   // pre-split tf32 (k,k+4) pairs
__device__ int g_counts[2][N_NODES];
__device__ int g_bucket[2][N_NODES * CAP];

// ---------------------------------------------------------------------------
// tf32 helpers
// ---------------------------------------------------------------------------
__device__ __forceinline__ unsigned f2tf32(float x) {
    unsigned r;
    asm("cvt.rna.tf32.f32 %0, %1;" : "=r"(r) : "f"(x));
    return r;
}

__device__ __forceinline__ void mma_tf32(float c[4],
                                         unsigned a0, unsigned a1, unsigned a2, unsigned a3,
                                         unsigned b0, unsigned b1) {
    asm volatile(
        "mma.sync.aligned.m16n8k8.row.col.f32.tf32.tf32.f32 "
        "{%0,%1,%2,%3}, {%4,%5,%6,%7}, {%8,%9}, {%0,%1,%2,%3};"
        : "+f"(c[0]), "+f"(c[1]), "+f"(c[2]), "+f"(c[3])
        : "r"(a0), "r"(a1), "r"(a2), "r"(a3), "r"(b0), "r"(b1));
}

// ---------------------------------------------------------------------------
// Prep kernel: zero counters + pooled output, AND pre-split all W layers into
// pair layout: pair p of row o holds (tf32 W[o][g*8+i], tf32 W[o][g*8+i+4]),
// g = p>>2, i = p&3.
// ---------------------------------------------------------------------------
__global__ void prep_kernel(int* c0, int* c1, float* out,
                            const float* __restrict__ Ws, uint2* __restrict__ Wpair) {
    int i = blockIdx.x * blockDim.x + threadIdx.x;
    if (i < N_NODES) { c0[i] = 0; c1[i] = 0; }
    if (i < NGRAPHS * D) out[i] = 0.0f;
    if (i < NLAYERS * D * 32) {                  // 8192 pairs
        int l = i >> 11;                          // / (64*32)
        int r = i & 2047;
        int o = r >> 5, p = r & 31;
        int k0 = (p >> 2) * 8 + (p & 3);
        const float* w = Ws + l * D * D + o * D;
        Wpair[(l * D + o) * PSTR + p] = make_uint2(f2tf32(w[k0]), f2tf32(w[k0 + 4]));
    }
}

__global__ void build_kernel(const int* __restrict__ src0, const int* __restrict__ dst0,
                             const int* __restrict__ src1, const int* __restrict__ dst1,
                             int* c0, int* c1, int* b0, int* b1) {
    int e = blockIdx.x * blockDim.x + threadIdx.x;
    if (e >= N_EDGES) return;
    if (blockIdx.y == 0) {
        int d = dst0[e];
        int slot = atomicAdd(&c0[d], 1);
        if (slot < CAP) b0[d * CAP + slot] = src0[e];
    } else {
        int d = dst1[e];
        int slot = atomicAdd(&c1[d], 1);
        if (slot < CAP) b1[d * CAP + slot] = src1[e];
    }
}

// ---------------------------------------------------------------------------
// GIN aggregate as pure gather: out[n] = x[n] + sum_{e: dst=n} x[src[e]]
// ROUND_TF32: round output to tf32 (bitwise = what the GEMM would cvt anyway),
// so the GEMM stages A with zero conversions.
// ---------------------------------------------------------------------------
template <bool ROUND_TF32>
__global__ void gather_kernel(const float4* __restrict__ x,
                              const int* __restrict__ cnt,
                              const int* __restrict__ bucket,
                              float4* __restrict__ out) {
    int lane = threadIdx.x & 15;
    int n = blockIdx.x * 16 + (threadIdx.x >> 4);
    if (n >= N_NODES) return;
    int deg = cnt[n];
    if (deg > CAP) deg = CAP;
    const int* __restrict__ lst = bucket + n * CAP;
    float4 acc = x[n * 16 + lane];
    int j = 0;
    for (; j + 4 <= deg; j += 4) {
        int s0 = lst[j];
        int s1 = lst[j + 1];
        int s2 = lst[j + 2];
        int s3 = lst[j + 3];
        float4 v0 = x[s0 * 16 + lane];
        float4 v1 = x[s1 * 16 + lane];
        float4 v2 = x[s2 * 16 + lane];
        float4 v3 = x[s3 * 16 + lane];
        acc.x += (v0.x + v1.x) + (v2.x + v3.x);
        acc.y += (v0.y + v1.y) + (v2.y + v3.y);
        acc.z += (v0.z + v1.z) + (v2.z + v3.z);
        acc.w += (v0.w + v1.w) + (v2.w + v3.w);
    }
    for (; j < deg; j++) {
        int s = lst[j];
        float4 v = x[s * 16 + lane];
        acc.x += v.x; acc.y += v.y; acc.z += v.z; acc.w += v.w;
    }
    if (ROUND_TF32) {
        acc.x = __uint_as_float(f2tf32(acc.x));
        acc.y = __uint_as_float(f2tf32(acc.y));
        acc.z = __uint_as_float(f2tf32(acc.z));
        acc.w = __uint_as_float(f2tf32(acc.w));
    }
    out[n * 16 + lane] = acc;
}

// ---------------------------------------------------------------------------
// out = relu(in @ W^T + b) via SINGLE-PASS TF32 MMA (m16n8k8).
// 128-node tile, 512 threads (16 warps = 8 m-tiles x 2 n-halves).
// A pre-rounded to tf32 by the gather -> staging is pure bit-copy reshuffle.
// W pre-split globally -> staging is pure uint4 copy. Zero cvt in this kernel.
// In-place safe (full tile staged before any store by this block).
// ---------------------------------------------------------------------------
__global__ void __launch_bounds__(512, 2)
gemm_relu_kernel(const float* __restrict__ in,
                 const uint4* __restrict__ Wp,    // [64][18] uint4 (pair layout)
                 const float* __restrict__ bias,
                 float* __restrict__ out) {
    extern __shared__ unsigned sm[];
    unsigned* sA = sm;                       // [128][PSTR] uint2: (tf32 k, tf32 k+4)
    unsigned* sW = sm + 128 * PSTR * 2;      // [64][PSTR] uint2
    const int tid = threadIdx.x;
    const int nodeBase = blockIdx.x * 128;

    // Stage W: pure uint4 copy (1152 uint4; pad pairs 32..35 never read).
    {
        uint4* dW = (uint4*)sW;
        for (int i = tid; i < WLAYER_U4; i += 512) {
            int row = i / WROW_U4, c = i % WROW_U4;   // compact src -> padded dst
            dW[row * (PSTR / 2) + c] = Wp[i];
        }
    }
    // Stage A tile: bit-copy reshuffle (values already tf32-rounded).
    for (int i = tid; i < 128 * 16; i += 512) {
        int r = i >> 4, kv = (i & 15) * 4;
        int node = nodeBase + r;
        float4 v = make_float4(0.f, 0.f, 0.f, 0.f);
        if (node < N_NODES) v = *(const float4*)&in[node * D + kv];
        int p0 = (kv >> 3) * 4;
        int half = (kv >> 2) & 1;
        unsigned* base = &sA[(r * PSTR + p0) * 2 + half];
        base[0] = __float_as_uint(v.x);
        base[2] = __float_as_uint(v.y);
        base[4] = __float_as_uint(v.z);
        base[6] = __float_as_uint(v.w);
    }
    __syncthreads();

    const int warp = tid >> 5;
    const int lane = tid & 31;
    const int grp  = lane >> 2;      // 0..7
    const int tig  = lane & 3;       // 0..3
    const int m    = warp & 7;       // m-tile: rows m*16 .. m*16+15
    const int h    = warp >> 3;      // n-half: dims h*32 .. h*32+31
    const int row0 = m * 16 + grp;
    const int row1 = row0 + 8;

    float c[4][4];
#pragma unroll
    for (int nt = 0; nt < 4; nt++)
#pragma unroll
        for (int q = 0; q < 4; q++) c[nt][q] = 0.f;

#pragma unroll
    for (int kc = 0; kc < 8; kc++) {
        const int p = kc * 4 + tig;
        uint2 a0 = *(const uint2*)&sA[(row0 * PSTR + p) * 2];   // (A[k], A[k+4])
        uint2 a1 = *(const uint2*)&sA[(row1 * PSTR + p) * 2];
#pragma unroll
        for (int nt = 0; nt < 4; nt++) {
            const int o = h * 32 + nt * 8 + grp;
            uint2 b = *(const uint2*)&sW[(o * PSTR + p) * 2];   // (W[k], W[k+4])
            mma_tf32(c[nt], a0.x, a1.x, a0.y, a1.y, b.x, b.y);
        }
    }

    // Epilogue: bias + relu + store (c0,c1 -> row0; c2,c3 -> row1)
    const int n0 = nodeBase + row0;
    const int n1 = nodeBase + row1;
#pragma unroll
    for (int nt = 0; nt < 4; nt++) {
        int o = h * 32 + nt * 8 + 2 * tig;
        float2 bv = *(const float2*)&bias[o];
        if (n0 < N_NODES) {
            float2 v = make_float2(fmaxf(c[nt][0] + bv.x, 0.f),
                                   fmaxf(c[nt][1] + bv.y, 0.f));
            *(float2*)&out[n0 * D + o] = v;
        }
        if (n1 < N_NODES) {
            float2 v = make_float2(fmaxf(c[nt][2] + bv.x, 0.f),
                                   fmaxf(c[nt][3] + bv.y, 0.f));
            *(float2*)&out[n1 * D + o] = v;
        }
    }
}

// ---------------------------------------------------------------------------
// batch is sorted: register accumulator, flush on graph-id change only.
// ---------------------------------------------------------------------------
__global__ void pool_kernel(const float* __restrict__ x,
                            const int* __restrict__ batch,
                            float* __restrict__ out, int chunk) {
    int d = threadIdx.x;
    int n0 = blockIdx.x * chunk;
    int n1 = n0 + chunk;
    if (n1 > N_NODES) n1 = N_NODES;
    if (n0 >= n1) return;
    float acc = 0.0f;
    int cur = batch[n0];
    for (int n = n0; n < n1; n++) {
        int g = batch[n];
        if (g != cur) {
            atomicAdd(&out[cur * D + d], acc);
            acc = 0.0f;
            cur = g;
        }
        acc += x[n * D + d];
    }
    atomicAdd(&out[cur * D + d], acc);
}

// ---------------------------------------------------------------------------
extern "C" void kernel_launch(void* const* d_in, const int* in_sizes, int n_in,
                              void* d_out, int out_size) {
    const float* x     = (const float*)d_in[0];
    const int*   ei    = (const int*)d_in[1];
    const int*   eei   = (const int*)d_in[2];
    const int*   batch = (const int*)d_in[3];
    const float* Ws    = (const float*)d_in[4];
    const float* bs    = (const float*)d_in[5];
    float*       out   = (float*)d_out;

    // Raise dynamic-smem limit (idempotent; not an allocation).
    cudaFuncSetAttribute(gemm_relu_kernel,
                         cudaFuncAttributeMaxDynamicSharedMemorySize, GEMM_SMEM_BYTES);

    float4 *bufA, *bufB;
    uint4* wpair;
    int *counts, *bucket;
    cudaGetSymbolAddress((void**)&bufA, g_bufA);
    cudaGetSymbolAddress((void**)&bufB, g_bufB);
    cudaGetSymbolAddress((void**)&wpair, g_Wpair);
    cudaGetSymbolAddress((void**)&counts, g_counts);
    cudaGetSymbolAddress((void**)&bucket, g_bucket);
    int *c0 = counts, *c1 = counts + N_NODES;
    int *b0 = bucket, *b1 = bucket + N_NODES * CAP;

    const int* src1 = ei;   const int* dst1 = ei + N_EDGES;
    const int* src2 = eei;  const int* dst2 = eei + N_EDGES;

    // ---- Prep (zero + W pre-split) + bucket adjacency build ----
    const int nBlocks = (N_NODES + 255) / 256;
    const int eBlocks = (N_EDGES + 255) / 256;
    prep_kernel<<<nBlocks, 256>>>(c0, c1, out, Ws, (uint2*)wpair);
    build_kernel<<<dim3(eBlocks, 2), 256>>>(src1, dst1, src2, dst2, c0, c1, b0, b1);

    // ---- 4 layers: real gather (tf32-rounded) -> TF32 GEMM (in place) -> expander gather ----
    const int gatherBlocks = (N_NODES + 15) / 16;
    const int gemmBlocks = (N_NODES + 127) / 128;

    const float4* xcur = (const float4*)x;
    for (int i = 0; i < NLAYERS; i++) {
        gather_kernel<true><<<gatherBlocks, 256>>>(xcur, c0, b0, bufB);
        gemm_relu_kernel<<<gemmBlocks, 512, GEMM_SMEM_BYTES>>>((const float*)bufB,
                                                               wpair + i * WLAYER_U4,
                                                               bs + i * D, (float*)bufB);
        gather_kernel<false><<<gatherBlocks, 256>>>(bufB, c1, b1, bufA);
        xcur = bufA;
    }

    pool_kernel<<<(N_NODES + 127) / 128, 64>>>((const float*)xcur, batch, out, 128);
}